// round 3
// baseline (speedup 1.0000x reference)
#include <cuda_runtime.h>
#include <cuda_bf16.h>

// ---------------------------------------------------------------------------
// Turbo decoder (log-MAP BCJR), 8-state RSC, B=256, K=6144, 6 iterations.
// Sliding-window parallel BCJR: C=96 chunks of L=64, warmup W=64.
// Time-major [t][B] layout for full coalescing. LLR convention log p0/p1.
// ---------------------------------------------------------------------------

constexpr int Kc = 6144;
constexpr int Bc = 256;
constexpr int Lc = 64;
constexpr int Wc = 64;
constexpr int Cc = Kc / Lc;   // 96 chunks
constexpr float NEGF = -1e30f;

// Static device scratch (no allocations anywhere).
__device__ float g_ls1[Kc * Bc];
__device__ float g_lp1[Kc * Bc];
__device__ float g_lp2[Kc * Bc];
__device__ float g_ls2[Kc * Bc];
__device__ float g_la1[Kc * Bc];
__device__ float g_la2[Kc * Bc];
__device__ float g_lpost[Kc * Bc];
__device__ float g_bn[Kc * 8 * Bc];   // beta_{t+1}, layout [t][state][b]
__device__ int   g_inv[Kc];

// ---------------------------------------------------------------------------
// log-sum-exp helpers (fast-math MUFU; ~1e-6 rel accuracy, gate is 1e-3)
// ---------------------------------------------------------------------------
__device__ __forceinline__ float lse2(float x, float y) {
    float mx = fmaxf(x, y);
    float d  = fabsf(x - y);
    return mx + __logf(1.0f + __expf(-d));
}

__device__ __forceinline__ float lse8(float m0, float m1, float m2, float m3,
                                      float m4, float m5, float m6, float m7) {
    float mx = fmaxf(fmaxf(fmaxf(m0, m1), fmaxf(m2, m3)),
                     fmaxf(fmaxf(m4, m5), fmaxf(m6, m7)));
    float s = __expf(m0 - mx) + __expf(m1 - mx) + __expf(m2 - mx) + __expf(m3 - mx)
            + __expf(m4 - mx) + __expf(m5 - mx) + __expf(m6 - mx) + __expf(m7 - mx);
    return mx + __logf(s);
}

// Trellis (G0=(1,0,1,1), G1=(1,1,0,1), MU=3), precomputed:
//   gamma(s,u=0) = g0 for s in {0,1,6,7}, g1 for s in {2,3,4,5}; gamma(s,1) = -gamma(s,0)
//   with g0 = 0.5*(lsu+lp), g1 = 0.5*(lsu-lp).
// next-state table: 0:(0,4) 1:(4,0) 2:(5,1) 3:(1,5) 4:(2,6) 5:(6,2) 6:(7,3) 7:(3,7)

__device__ __forceinline__ void fwd_step(float g0, float g1,
    float& A0, float& A1, float& A2, float& A3,
    float& A4, float& A5, float& A6, float& A7) {
    float n0 = lse2(A0 + g0, A1 - g0);
    float n4 = lse2(A0 - g0, A1 + g0);
    float n5 = lse2(A2 + g1, A3 - g1);
    float n1 = lse2(A2 - g1, A3 + g1);
    float n2 = lse2(A4 + g1, A5 - g1);
    float n6 = lse2(A4 - g1, A5 + g1);
    float n7 = lse2(A6 + g0, A7 - g0);
    float n3 = lse2(A6 - g0, A7 + g0);
    A0 = 0.0f;     A1 = n1 - n0;  A2 = n2 - n0;  A3 = n3 - n0;
    A4 = n4 - n0;  A5 = n5 - n0;  A6 = n6 - n0;  A7 = n7 - n0;
}

__device__ __forceinline__ void bwd_step(float g0, float g1,
    float& B0, float& B1, float& B2, float& B3,
    float& B4, float& B5, float& B6, float& B7) {
    float n0 = lse2(B0 + g0, B4 - g0);
    float n1 = lse2(B4 + g0, B0 - g0);
    float n2 = lse2(B5 + g1, B1 - g1);
    float n3 = lse2(B1 + g1, B5 - g1);
    float n4 = lse2(B2 + g1, B6 - g1);
    float n5 = lse2(B6 + g1, B2 - g1);
    float n6 = lse2(B7 + g0, B3 - g0);
    float n7 = lse2(B3 + g0, B7 - g0);
    B0 = 0.0f;     B1 = n1 - n0;  B2 = n2 - n0;  B3 = n3 - n0;
    B4 = n4 - n0;  B5 = n5 - n0;  B6 = n6 - n0;  B7 = n7 - n0;
}

// ---------------------------------------------------------------------------
// Setup kernels
// ---------------------------------------------------------------------------
__global__ void unpack_kernel(const float* __restrict__ in) {
    // in: [B][3K] row-major; produce time-major ls1/lp1/lp2 [t][B] (negated).
    __shared__ float tile[3][32][33];
    int t0 = blockIdx.x * 32;
    int b0 = blockIdx.y * 32;
    int tid = threadIdx.x;
    for (int e = tid; e < 32 * 96; e += 256) {
        int db  = e / 96;
        int off = e % 96;
        float v = in[(size_t)(b0 + db) * (3 * Kc) + 3 * t0 + off];
        tile[off % 3][off / 3][db] = -v;
    }
    __syncthreads();
    for (int e = tid; e < 3 * 32 * 32; e += 256) {
        int cc = e >> 10;
        int r  = e & 1023;
        int tt = r >> 5;
        int bb = r & 31;
        float v = tile[cc][tt][bb];
        float* dst = (cc == 0) ? g_ls1 : (cc == 1) ? g_lp1 : g_lp2;
        dst[(t0 + tt) * Bc + b0 + bb] = v;
    }
}

__global__ void build_inv_kernel(const int* __restrict__ perm) {
    int j = blockIdx.x * 256 + threadIdx.x;
    if (j < Kc) g_inv[perm[j]] = j;
}

__global__ void zero_la1_kernel() {
    int i = blockIdx.x * 256 + threadIdx.x;
    g_la1[i] = 0.0f;
}

__global__ void gather_ls2_kernel(const int* __restrict__ perm) {
    // ls2[j][b] = ls1[perm[j]][b]
    int b  = threadIdx.x;
    int j0 = blockIdx.x * 8;
    #pragma unroll
    for (int r = 0; r < 8; ++r)
        g_ls2[(j0 + r) * Bc + b] = g_ls1[perm[j0 + r] * Bc + b];
}

// ---------------------------------------------------------------------------
// BCJR backward: store beta_{t+1} (normalized) to g_bn for the chunk range
// ---------------------------------------------------------------------------
__global__ void __launch_bounds__(32) bcjr_bwd(int dec) {
    const float* __restrict__ ls = dec ? g_ls2 : g_ls1;
    const float* __restrict__ lp = dec ? g_lp2 : g_lp1;
    const float* __restrict__ la = dec ? g_la2 : g_la1;

    int b    = blockIdx.y * 32 + threadIdx.x;
    int c    = blockIdx.x;
    int t_lo = c * Lc;
    int t_sh = t_lo + Lc - 1;                       // highest stored index
    int t_hi = t_lo + Lc + Wc - 1;                  // warmup start
    if (t_hi > Kc - 1) t_hi = Kc - 1;               // clamp: uniform init == exact beta_K

    float B0 = 0, B1 = 0, B2 = 0, B3 = 0, B4 = 0, B5 = 0, B6 = 0, B7 = 0;

    #pragma unroll 2
    for (int t = t_hi; t > t_sh; --t) {             // warmup (no stores)
        int idx = t * Bc + b;
        float h = 0.5f * (ls[idx] + la[idx]);
        float q = 0.5f * lp[idx];
        bwd_step(h + q, h - q, B0, B1, B2, B3, B4, B5, B6, B7);
    }
    #pragma unroll 2
    for (int t = t_sh; t >= t_lo; --t) {            // main region
        float* p = g_bn + (size_t)t * 8 * Bc + b;
        p[0]      = B0; p[Bc]     = B1; p[2 * Bc] = B2; p[3 * Bc] = B3;
        p[4 * Bc] = B4; p[5 * Bc] = B5; p[6 * Bc] = B6; p[7 * Bc] = B7;
        int idx = t * Bc + b;
        float h = 0.5f * (ls[idx] + la[idx]);
        float q = 0.5f * lp[idx];
        bwd_step(h + q, h - q, B0, B1, B2, B3, B4, B5, B6, B7);
    }
}

// ---------------------------------------------------------------------------
// BCJR forward + posterior + extrinsic scatter.
//   dec==0: reads la1, writes g_la2[inv[t]] = lpost - la - ls
//   dec==1: reads la2, writes g_la1[perm[t]] = lpost - la - ls
//   last!=0: also store lpost (time-major) for the final output transpose.
// ---------------------------------------------------------------------------
__global__ void __launch_bounds__(32) bcjr_fwd(int dec, const int* __restrict__ perm, int last) {
    const float* __restrict__ ls = dec ? g_ls2 : g_ls1;
    const float* __restrict__ lp = dec ? g_lp2 : g_lp1;
    const float* __restrict__ la = dec ? g_la2 : g_la1;
    float* __restrict__ lout     = dec ? g_la1 : g_la2;
    const int* __restrict__ map  = dec ? perm : g_inv;

    int b  = blockIdx.y * 32 + threadIdx.x;
    int c  = blockIdx.x;
    int tm = c * Lc;
    int t0 = tm - Wc; if (t0 < 0) t0 = 0;

    float A0, A1, A2, A3, A4, A5, A6, A7;
    if (t0 == 0) { A0 = 0.0f; A1 = A2 = A3 = A4 = A5 = A6 = A7 = NEGF; }  // exact
    else         { A0 = A1 = A2 = A3 = A4 = A5 = A6 = A7 = 0.0f; }        // uniform

    #pragma unroll 2
    for (int t = t0; t < tm; ++t) {                 // warmup
        int idx = t * Bc + b;
        float h = 0.5f * (ls[idx] + la[idx]);
        float q = 0.5f * lp[idx];
        fwd_step(h + q, h - q, A0, A1, A2, A3, A4, A5, A6, A7);
    }

    #pragma unroll 2
    for (int t = tm; t < tm + Lc; ++t) {            // main region
        int idx = t * Bc + b;
        float lsv = ls[idx], lav = la[idx], lpv = lp[idx];
        float h  = 0.5f * (lsv + lav);
        float q  = 0.5f * lpv;
        float g0 = h + q, g1 = h - q;

        const float* p = g_bn + (size_t)t * 8 * Bc + b;
        float Bn0 = p[0];      float Bn1 = p[Bc];
        float Bn2 = p[2 * Bc]; float Bn3 = p[3 * Bc];
        float Bn4 = p[4 * Bc]; float Bn5 = p[5 * Bc];
        float Bn6 = p[6 * Bc]; float Bn7 = p[7 * Bc];

        // m[s,u] = alpha_t[s] + gamma(s,u) + beta_{t+1}[nxt(s,u)]
        float u0 = lse8(A0 + g0 + Bn0, A1 + g0 + Bn4,
                        A2 + g1 + Bn5, A3 + g1 + Bn1,
                        A4 + g1 + Bn2, A5 + g1 + Bn6,
                        A6 + g0 + Bn7, A7 + g0 + Bn3);
        float u1 = lse8(A0 - g0 + Bn4, A1 - g0 + Bn0,
                        A2 - g1 + Bn1, A3 - g1 + Bn5,
                        A4 - g1 + Bn6, A5 - g1 + Bn2,
                        A6 - g0 + Bn3, A7 - g0 + Bn7);
        float lpost = u0 - u1;

        lout[map[t] * Bc + b] = lpost - lav - lsv;
        if (last) g_lpost[idx] = lpost;

        fwd_step(g0, g1, A0, A1, A2, A3, A4, A5, A6, A7);
    }
}

// ---------------------------------------------------------------------------
// Output: out[b][i] = -lpost2[inv[i]][b]   (gather + transpose, both coalesced)
// ---------------------------------------------------------------------------
__global__ void output_kernel(float* __restrict__ out) {
    __shared__ float tile[32][33];
    int i0 = blockIdx.x * 32, b0 = blockIdx.y * 32;
    int tid = threadIdx.x;
    for (int e = tid; e < 1024; e += 256) {
        int ii = e >> 5, bb = e & 31;
        tile[ii][bb] = -g_lpost[g_inv[i0 + ii] * Bc + b0 + bb];
    }
    __syncthreads();
    for (int e = tid; e < 1024; e += 256) {
        int bb = e >> 5, ii = e & 31;
        out[(size_t)(b0 + bb) * Kc + i0 + ii] = tile[ii][bb];
    }
}

// ---------------------------------------------------------------------------
extern "C" void kernel_launch(void* const* d_in, const int* in_sizes, int n_in,
                              void* d_out, int out_size) {
    const float* in  = (const float*)d_in[0];
    const int* perm  = (const int*)d_in[1];
    float* out       = (float*)d_out;

    dim3 upg(Kc / 32, Bc / 32);
    unpack_kernel<<<upg, 256>>>(in);
    build_inv_kernel<<<Kc / 256, 256>>>(perm);
    zero_la1_kernel<<<(Kc * Bc) / 256, 256>>>();
    gather_ls2_kernel<<<Kc / 8, 256>>>(perm);

    dim3 bg(Cc, Bc / 32);
    for (int it = 0; it < 6; ++it) {
        bcjr_bwd<<<bg, 32>>>(0);
        bcjr_fwd<<<bg, 32>>>(0, perm, 0);
        bcjr_bwd<<<bg, 32>>>(1);
        bcjr_fwd<<<bg, 32>>>(1, perm, (it == 5) ? 1 : 0);
    }

    dim3 og(Kc / 32, Bc / 32);
    output_kernel<<<og, 256>>>(out);
}

// round 4
// speedup vs baseline: 1.4308x; 1.4308x over previous
#include <cuda_runtime.h>
#include <cuda_bf16.h>

// ---------------------------------------------------------------------------
// Turbo decoder (log-MAP BCJR), 8-state RSC, B=256, K=6144, 6 iterations.
// Fused sliding-window BCJR: per chunk (L=32, warmup W=32) one kernel does
// backward recursion (beta kept in SMEM, same thread produces & consumes)
// then forward recursion + posterior + extrinsic scatter.
// Time-major [t][B] layout for full coalescing. LLR convention log p0/p1.
// ---------------------------------------------------------------------------

constexpr int Kc = 6144;
constexpr int Bc = 256;
constexpr int Lc = 32;
constexpr int Wc = 32;
constexpr int Cc = Kc / Lc;   // 192 chunks
constexpr float NEGF = -1e30f;

// Static device scratch (no allocations anywhere).
__device__ float g_ls1[Kc * Bc];
__device__ float g_lp1[Kc * Bc];
__device__ float g_lp2[Kc * Bc];
__device__ float g_ls2[Kc * Bc];
__device__ float g_la1[Kc * Bc];
__device__ float g_la2[Kc * Bc];
__device__ float g_lpost[Kc * Bc];
__device__ int   g_inv[Kc];

// ---------------------------------------------------------------------------
// log-sum-exp helpers (fast-math MUFU; ~1e-6 rel accuracy, gate is 1e-3)
// ---------------------------------------------------------------------------
__device__ __forceinline__ float lse2(float x, float y) {
    float mx = fmaxf(x, y);
    float d  = fabsf(x - y);
    return mx + __logf(1.0f + __expf(-d));
}

__device__ __forceinline__ float lse8(float m0, float m1, float m2, float m3,
                                      float m4, float m5, float m6, float m7) {
    float mx = fmaxf(fmaxf(fmaxf(m0, m1), fmaxf(m2, m3)),
                     fmaxf(fmaxf(m4, m5), fmaxf(m6, m7)));
    float s = __expf(m0 - mx) + __expf(m1 - mx) + __expf(m2 - mx) + __expf(m3 - mx)
            + __expf(m4 - mx) + __expf(m5 - mx) + __expf(m6 - mx) + __expf(m7 - mx);
    return mx + __logf(s);
}

// Trellis (G0=(1,0,1,1), G1=(1,1,0,1), MU=3), precomputed:
//   gamma(s,u=0) = g0 for s in {0,1,6,7}, g1 for s in {2,3,4,5}; gamma(s,1) = -gamma(s,0)
//   with g0 = 0.5*(lsu+lp), g1 = 0.5*(lsu-lp).
// next-state table: 0:(0,4) 1:(4,0) 2:(5,1) 3:(1,5) 4:(2,6) 5:(6,2) 6:(7,3) 7:(3,7)

__device__ __forceinline__ void fwd_step(float g0, float g1,
    float& A0, float& A1, float& A2, float& A3,
    float& A4, float& A5, float& A6, float& A7) {
    float n0 = lse2(A0 + g0, A1 - g0);
    float n4 = lse2(A0 - g0, A1 + g0);
    float n5 = lse2(A2 + g1, A3 - g1);
    float n1 = lse2(A2 - g1, A3 + g1);
    float n2 = lse2(A4 + g1, A5 - g1);
    float n6 = lse2(A4 - g1, A5 + g1);
    float n7 = lse2(A6 + g0, A7 - g0);
    float n3 = lse2(A6 - g0, A7 + g0);
    A0 = 0.0f;     A1 = n1 - n0;  A2 = n2 - n0;  A3 = n3 - n0;
    A4 = n4 - n0;  A5 = n5 - n0;  A6 = n6 - n0;  A7 = n7 - n0;
}

__device__ __forceinline__ void bwd_step(float g0, float g1,
    float& B0, float& B1, float& B2, float& B3,
    float& B4, float& B5, float& B6, float& B7) {
    float n0 = lse2(B0 + g0, B4 - g0);
    float n1 = lse2(B4 + g0, B0 - g0);
    float n2 = lse2(B5 + g1, B1 - g1);
    float n3 = lse2(B1 + g1, B5 - g1);
    float n4 = lse2(B2 + g1, B6 - g1);
    float n5 = lse2(B6 + g1, B2 - g1);
    float n6 = lse2(B7 + g0, B3 - g0);
    float n7 = lse2(B3 + g0, B7 - g0);
    B0 = 0.0f;     B1 = n1 - n0;  B2 = n2 - n0;  B3 = n3 - n0;
    B4 = n4 - n0;  B5 = n5 - n0;  B6 = n6 - n0;  B7 = n7 - n0;
}

// ---------------------------------------------------------------------------
// Setup kernels
// ---------------------------------------------------------------------------
__global__ void unpack_kernel(const float* __restrict__ in) {
    // in: [B][3K] row-major; produce time-major ls1/lp1/lp2 [t][B] (negated).
    // Also zeroes g_la1 for iteration 0.
    __shared__ float tile[3][32][33];
    int t0 = blockIdx.x * 32;
    int b0 = blockIdx.y * 32;
    int tid = threadIdx.x;
    for (int e = tid; e < 32 * 96; e += 256) {
        int db  = e / 96;
        int off = e % 96;
        float v = in[(size_t)(b0 + db) * (3 * Kc) + 3 * t0 + off];
        tile[off % 3][off / 3][db] = -v;
    }
    __syncthreads();
    for (int e = tid; e < 3 * 32 * 32; e += 256) {
        int cc = e >> 10;
        int r  = e & 1023;
        int tt = r >> 5;
        int bb = r & 31;
        float v = tile[cc][tt][bb];
        float* dst = (cc == 0) ? g_ls1 : (cc == 1) ? g_lp1 : g_lp2;
        dst[(t0 + tt) * Bc + b0 + bb] = v;
    }
    for (int e = tid; e < 1024; e += 256) {
        int tt = e >> 5, bb = e & 31;
        g_la1[(t0 + tt) * Bc + b0 + bb] = 0.0f;
    }
}

__global__ void build_inv_kernel(const int* __restrict__ perm) {
    int j = blockIdx.x * 256 + threadIdx.x;
    if (j < Kc) g_inv[perm[j]] = j;
}

__global__ void gather_ls2_kernel(const int* __restrict__ perm) {
    // ls2[j][b] = ls1[perm[j]][b]
    int b  = threadIdx.x;
    int j0 = blockIdx.x * 8;
    #pragma unroll
    for (int r = 0; r < 8; ++r)
        g_ls2[(j0 + r) * Bc + b] = g_ls1[perm[j0 + r] * Bc + b];
}

// ---------------------------------------------------------------------------
// Fused BCJR pass (one decoder half-iteration):
//   backward recursion over [t_lo .. t_lo+L+W-1] storing normalized beta_{t+1}
//   for the main region into SMEM, then forward recursion with warmup,
//   posterior LLR, and extrinsic scatter through the interleaver map.
//   dec==0: reads la1, writes g_la2[inv[t]] = lpost - la - ls
//   dec==1: reads la2, writes g_la1[perm[t]] = lpost - la - ls
//   last!=0: also store lpost (time-major) for the final output transpose.
// Each thread owns one b end-to-end -> beta producer == consumer, no syncs.
// ---------------------------------------------------------------------------
__global__ void __launch_bounds__(32) bcjr_pass(int dec, const int* __restrict__ perm, int last) {
    __shared__ float sbeta[Lc * 8 * 32];   // [t_rel][state][lane], 32 KB

    const float* __restrict__ ls = dec ? g_ls2 : g_ls1;
    const float* __restrict__ lp = dec ? g_lp2 : g_lp1;
    const float* __restrict__ la = dec ? g_la2 : g_la1;
    float* __restrict__ lout     = dec ? g_la1 : g_la2;
    const int* __restrict__ map  = dec ? perm : g_inv;

    int lane = threadIdx.x;
    int b    = blockIdx.y * 32 + lane;
    int c    = blockIdx.x;
    int t_lo = c * Lc;
    int t_sh = t_lo + Lc - 1;

    // ---------------- backward ----------------
    {
        int t_hi = t_lo + Lc + Wc - 1;
        if (t_hi > Kc - 1) t_hi = Kc - 1;   // clamp: uniform init == exact beta_K

        float B0 = 0, B1 = 0, B2 = 0, B3 = 0, B4 = 0, B5 = 0, B6 = 0, B7 = 0;

        #pragma unroll 4
        for (int t = t_hi; t > t_sh; --t) {             // warmup (no stores)
            int idx = t * Bc + b;
            float h = 0.5f * (ls[idx] + la[idx]);
            float q = 0.5f * lp[idx];
            bwd_step(h + q, h - q, B0, B1, B2, B3, B4, B5, B6, B7);
        }
        #pragma unroll 4
        for (int t = t_sh; t >= t_lo; --t) {            // main region -> SMEM
            float* p = &sbeta[(t - t_lo) * 256 + lane];
            p[0]   = B0; p[32]  = B1; p[64]  = B2; p[96]  = B3;
            p[128] = B4; p[160] = B5; p[192] = B6; p[224] = B7;
            int idx = t * Bc + b;
            float h = 0.5f * (ls[idx] + la[idx]);
            float q = 0.5f * lp[idx];
            bwd_step(h + q, h - q, B0, B1, B2, B3, B4, B5, B6, B7);
        }
    }

    // ---------------- forward + posterior ----------------
    {
        int t0 = t_lo - Wc; if (t0 < 0) t0 = 0;

        float A0, A1, A2, A3, A4, A5, A6, A7;
        if (t0 == 0) { A0 = 0.0f; A1 = A2 = A3 = A4 = A5 = A6 = A7 = NEGF; }  // exact
        else         { A0 = A1 = A2 = A3 = A4 = A5 = A6 = A7 = 0.0f; }        // uniform

        #pragma unroll 4
        for (int t = t0; t < t_lo; ++t) {               // warmup
            int idx = t * Bc + b;
            float h = 0.5f * (ls[idx] + la[idx]);
            float q = 0.5f * lp[idx];
            fwd_step(h + q, h - q, A0, A1, A2, A3, A4, A5, A6, A7);
        }

        #pragma unroll 2
        for (int t = t_lo; t <= t_sh; ++t) {            // main region
            int idx = t * Bc + b;
            float lsv = ls[idx], lav = la[idx], lpv = lp[idx];
            float h  = 0.5f * (lsv + lav);
            float q  = 0.5f * lpv;
            float g0 = h + q, g1 = h - q;

            const float* p = &sbeta[(t - t_lo) * 256 + lane];
            float Bn0 = p[0];   float Bn1 = p[32];
            float Bn2 = p[64];  float Bn3 = p[96];
            float Bn4 = p[128]; float Bn5 = p[160];
            float Bn6 = p[192]; float Bn7 = p[224];

            // m[s,u] = alpha_t[s] + gamma(s,u) + beta_{t+1}[nxt(s,u)]
            float u0 = lse8(A0 + g0 + Bn0, A1 + g0 + Bn4,
                            A2 + g1 + Bn5, A3 + g1 + Bn1,
                            A4 + g1 + Bn2, A5 + g1 + Bn6,
                            A6 + g0 + Bn7, A7 + g0 + Bn3);
            float u1 = lse8(A0 - g0 + Bn4, A1 - g0 + Bn0,
                            A2 - g1 + Bn1, A3 - g1 + Bn5,
                            A4 - g1 + Bn6, A5 - g1 + Bn2,
                            A6 - g0 + Bn3, A7 - g0 + Bn7);
            float lpost = u0 - u1;

            lout[map[t] * Bc + b] = lpost - lav - lsv;
            if (last) g_lpost[idx] = lpost;

            fwd_step(g0, g1, A0, A1, A2, A3, A4, A5, A6, A7);
        }
    }
}

// ---------------------------------------------------------------------------
// Output: out[b][i] = -lpost2[inv[i]][b]   (gather + transpose, both coalesced)
// ---------------------------------------------------------------------------
__global__ void output_kernel(float* __restrict__ out) {
    __shared__ float tile[32][33];
    int i0 = blockIdx.x * 32, b0 = blockIdx.y * 32;
    int tid = threadIdx.x;
    for (int e = tid; e < 1024; e += 256) {
        int ii = e >> 5, bb = e & 31;
        tile[ii][bb] = -g_lpost[g_inv[i0 + ii] * Bc + b0 + bb];
    }
    __syncthreads();
    for (int e = tid; e < 1024; e += 256) {
        int bb = e >> 5, ii = e & 31;
        out[(size_t)(b0 + bb) * Kc + i0 + ii] = tile[ii][bb];
    }
}

// ---------------------------------------------------------------------------
extern "C" void kernel_launch(void* const* d_in, const int* in_sizes, int n_in,
                              void* d_out, int out_size) {
    const float* in  = (const float*)d_in[0];
    const int* perm  = (const int*)d_in[1];
    float* out       = (float*)d_out;

    dim3 upg(Kc / 32, Bc / 32);
    unpack_kernel<<<upg, 256>>>(in);
    build_inv_kernel<<<Kc / 256, 256>>>(perm);
    gather_ls2_kernel<<<Kc / 8, 256>>>(perm);

    dim3 bg(Cc, Bc / 32);   // 192 x 8 one-warp blocks
    for (int it = 0; it < 6; ++it) {
        bcjr_pass<<<bg, 32>>>(0, perm, 0);
        bcjr_pass<<<bg, 32>>>(1, perm, (it == 5) ? 1 : 0);
    }

    dim3 og(Kc / 32, Bc / 32);
    output_kernel<<<og, 256>>>(out);
}

// round 5
// speedup vs baseline: 3.4284x; 2.3961x over previous
#include <cuda_runtime.h>
#include <cuda_bf16.h>
#include <cuda_fp16.h>

// ---------------------------------------------------------------------------
// Turbo decoder (linear-domain BCJR), 8-state RSC, B=256, K=6144, 6 iters.
// Fused sliding-window BCJR per chunk (L=32, W=32): backward recursion with
// normalized state probabilities kept in SMEM as half2, then forward
// recursion + posterior + extrinsic scatter. One warp per (chunk, b-tile);
// each thread owns one b end-to-end (beta producer == consumer, no syncs).
// Time-major [t][B] layout for full coalescing. LLR convention log p0/p1.
// ---------------------------------------------------------------------------

constexpr int Kc = 6144;
constexpr int Bc = 256;
constexpr int Lc = 32;
constexpr int Wc = 32;
constexpr int Cc = Kc / Lc;   // 192 chunks

// Static device scratch (no allocations anywhere).
__device__ float g_ls1[Kc * Bc];
__device__ float g_lp1[Kc * Bc];
__device__ float g_lp2[Kc * Bc];
__device__ float g_ls2[Kc * Bc];
__device__ float g_la1[Kc * Bc];
__device__ float g_la2[Kc * Bc];
__device__ float g_lpost[Kc * Bc];
__device__ int   g_inv[Kc];

// ---------------------------------------------------------------------------
// Branch probabilities (offset by m so all exp args <= 0; m-scale cancels
// in normalization and in the posterior log-ratio).
//   g0 = 0.5*(lsu+lp), g1 = 0.5*(lsu-lp)
// ---------------------------------------------------------------------------
__device__ __forceinline__ void branch_probs(float lsv, float lav, float lpv,
    float& e0p, float& e0n, float& e1p, float& e1n) {
    float h  = 0.5f * (lsv + lav);
    float q  = 0.5f * lpv;
    float g0 = h + q, g1 = h - q;
    float m  = fminf(fmaxf(fabsf(g0), fabsf(g1)), 60.0f);
    e0p = __expf(g0 - m);  e0n = __expf(-g0 - m);
    e1p = __expf(g1 - m);  e1n = __expf(-g1 - m);
}

// Trellis (G0=(1,0,1,1), G1=(1,1,0,1), MU=3):
//   branch prob for (s,u=0) is e0p for s in {0,1,6,7}, e1p for s in {2,3,4,5};
//   u=1 uses the matching e*n. next: 0:(0,4) 1:(4,0) 2:(5,1) 3:(1,5)
//   4:(2,6) 5:(6,2) 6:(7,3) 7:(3,7)

__device__ __forceinline__ void fwd_step_lin(
    float e0p, float e0n, float e1p, float e1n,
    float& a0, float& a1, float& a2, float& a3,
    float& a4, float& a5, float& a6, float& a7) {
    float n0 = a0 * e0p + a1 * e0n;
    float n4 = a0 * e0n + a1 * e0p;
    float n5 = a2 * e1p + a3 * e1n;
    float n1 = a2 * e1n + a3 * e1p;
    float n2 = a4 * e1p + a5 * e1n;
    float n6 = a4 * e1n + a5 * e1p;
    float n7 = a6 * e0p + a7 * e0n;
    float n3 = a6 * e0n + a7 * e0p;
    float s  = ((n0 + n1) + (n2 + n3)) + ((n4 + n5) + (n6 + n7));
    float r  = __fdividef(1.0f, s + 1e-38f);
    a0 = n0 * r; a1 = n1 * r; a2 = n2 * r; a3 = n3 * r;
    a4 = n4 * r; a5 = n5 * r; a6 = n6 * r; a7 = n7 * r;
}

__device__ __forceinline__ void bwd_step_lin(
    float e0p, float e0n, float e1p, float e1n,
    float& b0, float& b1, float& b2, float& b3,
    float& b4, float& b5, float& b6, float& b7) {
    float n0 = b0 * e0p + b4 * e0n;
    float n1 = b4 * e0p + b0 * e0n;
    float n2 = b5 * e1p + b1 * e1n;
    float n3 = b1 * e1p + b5 * e1n;
    float n4 = b2 * e1p + b6 * e1n;
    float n5 = b6 * e1p + b2 * e1n;
    float n6 = b7 * e0p + b3 * e0n;
    float n7 = b3 * e0p + b7 * e0n;
    float s  = ((n0 + n1) + (n2 + n3)) + ((n4 + n5) + (n6 + n7));
    float r  = __fdividef(1.0f, s + 1e-38f);
    b0 = n0 * r; b1 = n1 * r; b2 = n2 * r; b3 = n3 * r;
    b4 = n4 * r; b5 = n5 * r; b6 = n6 * r; b7 = n7 * r;
}

// ---------------------------------------------------------------------------
// Setup kernels
// ---------------------------------------------------------------------------
__global__ void unpack_kernel(const float* __restrict__ in) {
    // in: [B][3K] row-major; produce time-major ls1/lp1/lp2 [t][B] (negated).
    // Also zeroes g_la1 for iteration 0.
    __shared__ float tile[3][32][33];
    int t0 = blockIdx.x * 32;
    int b0 = blockIdx.y * 32;
    int tid = threadIdx.x;
    for (int e = tid; e < 32 * 96; e += 256) {
        int db  = e / 96;
        int off = e % 96;
        float v = in[(size_t)(b0 + db) * (3 * Kc) + 3 * t0 + off];
        tile[off % 3][off / 3][db] = -v;
    }
    __syncthreads();
    for (int e = tid; e < 3 * 32 * 32; e += 256) {
        int cc = e >> 10;
        int r  = e & 1023;
        int tt = r >> 5;
        int bb = r & 31;
        float v = tile[cc][tt][bb];
        float* dst = (cc == 0) ? g_ls1 : (cc == 1) ? g_lp1 : g_lp2;
        dst[(t0 + tt) * Bc + b0 + bb] = v;
    }
    for (int e = tid; e < 1024; e += 256) {
        int tt = e >> 5, bb = e & 31;
        g_la1[(t0 + tt) * Bc + b0 + bb] = 0.0f;
    }
}

__global__ void build_inv_kernel(const int* __restrict__ perm) {
    int j = blockIdx.x * 256 + threadIdx.x;
    if (j < Kc) g_inv[perm[j]] = j;
}

__global__ void gather_ls2_kernel(const int* __restrict__ perm) {
    // ls2[j][b] = ls1[perm[j]][b]
    int b  = threadIdx.x;
    int j0 = blockIdx.x * 8;
    #pragma unroll
    for (int r = 0; r < 8; ++r)
        g_ls2[(j0 + r) * Bc + b] = g_ls1[perm[j0 + r] * Bc + b];
}

// ---------------------------------------------------------------------------
// Fused BCJR pass (one decoder half-iteration), linear domain.
//   dec==0: reads la1, writes g_la2[inv[t]] = lpost - la - ls
//   dec==1: reads la2, writes g_la1[perm[t]] = lpost - la - ls
//   last!=0: also store lpost (time-major) for the final output transpose.
// ---------------------------------------------------------------------------
__global__ void __launch_bounds__(32) bcjr_pass(int dec, const int* __restrict__ perm, int last) {
    __shared__ __half2 sbeta[Lc * 4 * 32];   // [t_rel][pair][lane], 16 KB

    const float* __restrict__ ls = dec ? g_ls2 : g_ls1;
    const float* __restrict__ lp = dec ? g_lp2 : g_lp1;
    const float* __restrict__ la = dec ? g_la2 : g_la1;
    float* __restrict__ lout     = dec ? g_la1 : g_la2;
    const int* __restrict__ map  = dec ? perm : g_inv;

    int lane = threadIdx.x;
    int b    = blockIdx.y * 32 + lane;
    int c    = blockIdx.x;
    int t_lo = c * Lc;
    int t_sh = t_lo + Lc - 1;

    // ---------------- backward ----------------
    {
        int t_hi = t_lo + Lc + Wc - 1;
        if (t_hi > Kc - 1) t_hi = Kc - 1;   // clamp: uniform init == exact beta_K

        float B0 = 0.125f, B1 = 0.125f, B2 = 0.125f, B3 = 0.125f;
        float B4 = 0.125f, B5 = 0.125f, B6 = 0.125f, B7 = 0.125f;

        #pragma unroll 4
        for (int t = t_hi; t > t_sh; --t) {             // warmup (no stores)
            int idx = t * Bc + b;
            float e0p, e0n, e1p, e1n;
            branch_probs(ls[idx], la[idx], lp[idx], e0p, e0n, e1p, e1n);
            bwd_step_lin(e0p, e0n, e1p, e1n, B0, B1, B2, B3, B4, B5, B6, B7);
        }
        #pragma unroll 4
        for (int t = t_sh; t >= t_lo; --t) {            // main region -> SMEM
            __half2* p = &sbeta[(t - t_lo) * 128 + lane];
            p[0]  = __floats2half2_rn(B0, B1);
            p[32] = __floats2half2_rn(B2, B3);
            p[64] = __floats2half2_rn(B4, B5);
            p[96] = __floats2half2_rn(B6, B7);
            int idx = t * Bc + b;
            float e0p, e0n, e1p, e1n;
            branch_probs(ls[idx], la[idx], lp[idx], e0p, e0n, e1p, e1n);
            bwd_step_lin(e0p, e0n, e1p, e1n, B0, B1, B2, B3, B4, B5, B6, B7);
        }
    }

    // ---------------- forward + posterior ----------------
    {
        int t0 = t_lo - Wc; if (t0 < 0) t0 = 0;

        float a0, a1, a2, a3, a4, a5, a6, a7;
        if (t0 == 0) { a0 = 1.0f; a1 = a2 = a3 = a4 = a5 = a6 = a7 = 0.0f; }  // exact
        else { a0 = a1 = a2 = a3 = a4 = a5 = a6 = a7 = 0.125f; }              // uniform

        #pragma unroll 4
        for (int t = t0; t < t_lo; ++t) {               // warmup
            int idx = t * Bc + b;
            float e0p, e0n, e1p, e1n;
            branch_probs(ls[idx], la[idx], lp[idx], e0p, e0n, e1p, e1n);
            fwd_step_lin(e0p, e0n, e1p, e1n, a0, a1, a2, a3, a4, a5, a6, a7);
        }

        #pragma unroll 4
        for (int t = t_lo; t <= t_sh; ++t) {            // main region
            int idx = t * Bc + b;
            float lsv = ls[idx], lav = la[idx], lpv = lp[idx];
            float e0p, e0n, e1p, e1n;
            branch_probs(lsv, lav, lpv, e0p, e0n, e1p, e1n);

            const __half2* p = &sbeta[(t - t_lo) * 128 + lane];
            float2 q01 = __half22float2(p[0]);
            float2 q23 = __half22float2(p[32]);
            float2 q45 = __half22float2(p[64]);
            float2 q67 = __half22float2(p[96]);
            float bn0 = q01.x, bn1 = q01.y, bn2 = q23.x, bn3 = q23.y;
            float bn4 = q45.x, bn5 = q45.y, bn6 = q67.x, bn7 = q67.y;

            // u_k = sum_s alpha[s] * p(s,u=k) * beta[nxt(s,k)]
            float u0 = e0p * (a0 * bn0 + a1 * bn4 + a6 * bn7 + a7 * bn3)
                     + e1p * (a2 * bn5 + a3 * bn1 + a4 * bn2 + a5 * bn6);
            float u1 = e0n * (a0 * bn4 + a1 * bn0 + a6 * bn3 + a7 * bn7)
                     + e1n * (a2 * bn1 + a3 * bn5 + a4 * bn6 + a5 * bn2);
            float lpost = __logf(fmaxf(u0, 1e-38f)) - __logf(fmaxf(u1, 1e-38f));

            lout[map[t] * Bc + b] = lpost - lav - lsv;
            if (last) g_lpost[idx] = lpost;

            fwd_step_lin(e0p, e0n, e1p, e1n, a0, a1, a2, a3, a4, a5, a6, a7);
        }
    }
}

// ---------------------------------------------------------------------------
// Output: out[b][i] = -lpost2[inv[i]][b]   (gather + transpose, both coalesced)
// ---------------------------------------------------------------------------
__global__ void output_kernel(float* __restrict__ out) {
    __shared__ float tile[32][33];
    int i0 = blockIdx.x * 32, b0 = blockIdx.y * 32;
    int tid = threadIdx.x;
    for (int e = tid; e < 1024; e += 256) {
        int ii = e >> 5, bb = e & 31;
        tile[ii][bb] = -g_lpost[g_inv[i0 + ii] * Bc + b0 + bb];
    }
    __syncthreads();
    for (int e = tid; e < 1024; e += 256) {
        int bb = e >> 5, ii = e & 31;
        out[(size_t)(b0 + bb) * Kc + i0 + ii] = tile[ii][bb];
    }
}

// ---------------------------------------------------------------------------
extern "C" void kernel_launch(void* const* d_in, const int* in_sizes, int n_in,
                              void* d_out, int out_size) {
    const float* in  = (const float*)d_in[0];
    const int* perm  = (const int*)d_in[1];
    float* out       = (float*)d_out;

    dim3 upg(Kc / 32, Bc / 32);
    unpack_kernel<<<upg, 256>>>(in);
    build_inv_kernel<<<Kc / 256, 256>>>(perm);
    gather_ls2_kernel<<<Kc / 8, 256>>>(perm);

    dim3 bg(Cc, Bc / 32);   // 192 x 8 one-warp blocks (all resident in one wave)
    for (int it = 0; it < 6; ++it) {
        bcjr_pass<<<bg, 32>>>(0, perm, 0);
        bcjr_pass<<<bg, 32>>>(1, perm, (it == 5) ? 1 : 0);
    }

    dim3 og(Kc / 32, Bc / 32);
    output_kernel<<<og, 256>>>(out);
}